// round 13
// baseline (speedup 1.0000x reference)
#include <cuda_runtime.h>
#include <cuda_fp16.h>
#include <cstdint>

// ============================================================================
// Device scratch
// ============================================================================
__device__ float g_wm1[3456];
__device__ float g_fwm1[524288];
__device__ float g_fwm2[10240];

__device__ __align__(16) __half g_w2h[294912];
__device__ __align__(16) __half g_w3h[1179648];

__device__ __align__(16) __half g_h1[64u*64u*64u*128u];
__device__ __align__(16) __half g_h2[64u*32u*32u*256u];
__device__ float g_pool[64 * 512];
__device__ float g_a1[64 * 1024];

__device__ unsigned g_hist5[5][65536];
__device__ unsigned g_done[5];
struct Sel {
    unsigned b1, rank1, tbits, r, tieCount, idxThresh;
    unsigned tieIdx[2048];
};
__device__ Sel g_sel5[5];

struct MaskArgs {
    const float* s[5];
    const float* w[5];
    float* wm[5];
    int n[5];
    unsigned j[5];
};
struct ConvApply {
    const float* s[2];
    const float* w[2];
    __half* dst[2];
    int n[2];
    int cin[2];
};

__device__ __forceinline__ unsigned hperm(unsigned v) {
    return (v & 63u) * 1024u + (v >> 6);
}

// ============================================================================
// Persistent streams/events
// ============================================================================
struct GpuRes {
    cudaStream_t sA, sB;
    cudaEvent_t evStart, evW2, evW3, evFC;
    GpuRes() {
        cudaStreamCreateWithFlags(&sA, cudaStreamNonBlocking);
        cudaStreamCreateWithFlags(&sB, cudaStreamNonBlocking);
        cudaEventCreateWithFlags(&evStart, cudaEventDisableTiming);
        cudaEventCreateWithFlags(&evW2, cudaEventDisableTiming);
        cudaEventCreateWithFlags(&evW3, cudaEventDisableTiming);
        cudaEventCreateWithFlags(&evFC, cudaEventDisableTiming);
    }
};
static GpuRes g_res;

// ============================================================================
// PTX helpers
// ============================================================================
#define SWZ(o) ((o) ^ (((o) >> 3) & 0x70))

__device__ __forceinline__ uint32_t smem_u32(const void* p) {
    uint32_t a;
    asm("{ .reg .u64 t; cvta.to.shared.u64 t, %1; cvt.u32.u64 %0, t; }"
        : "=r"(a) : "l"(p));
    return a;
}
__device__ __forceinline__ void cp_async16(uint32_t dst, const void* src, bool inb) {
    int sz = inb ? 16 : 0;
    asm volatile("cp.async.cg.shared.global [%0], [%1], 16, %2;\n"
                 :: "r"(dst), "l"(src), "r"(sz));
}
__device__ __forceinline__ void cp_commit() {
    asm volatile("cp.async.commit_group;\n" ::: "memory");
}
__device__ __forceinline__ void ldsm4(uint32_t* r, uint32_t addr) {
    asm volatile("ldmatrix.sync.aligned.m8n8.x4.shared.b16 {%0,%1,%2,%3}, [%4];"
                 : "=r"(r[0]), "=r"(r[1]), "=r"(r[2]), "=r"(r[3]) : "r"(addr));
}
__device__ __forceinline__ void mma16816(float* d, const uint32_t* a,
                                         uint32_t b0, uint32_t b1) {
    asm volatile(
        "mma.sync.aligned.m16n8k16.row.col.f32.f16.f16.f32 "
        "{%0,%1,%2,%3}, {%4,%5,%6,%7}, {%8,%9}, {%0,%1,%2,%3};"
        : "+f"(d[0]), "+f"(d[1]), "+f"(d[2]), "+f"(d[3])
        : "r"(a[0]), "r"(a[1]), "r"(a[2]), "r"(a[3]), "r"(b0), "r"(b1));
}

// ============================================================================
// k_mask0: exact select+apply for conv1 scores (n=3456, j=1728), 1 block.
// ============================================================================
__global__ __launch_bounds__(256) void k_mask0(const float* __restrict__ s,
                                               const float* __restrict__ w,
                                               float* __restrict__ wm) {
    constexpr int N = 3456;
    constexpr unsigned J = 1728;
    __shared__ unsigned sv[N];
    __shared__ unsigned wred[8];
    __shared__ unsigned t_sh, r_sh, tieCnt, idx_sh;
    __shared__ unsigned tieIdx[128];
    const int tid = threadIdx.x;
    const int lane = tid & 31, wid = tid >> 5;

    for (int i = tid; i < N; i += 256) sv[i] = __float_as_uint(fabsf(s[i]));
    if (tid == 0) { t_sh = 0; r_sh = J; }
    __syncthreads();

    for (int bit = 31; bit >= 0; bit--) {
        const unsigned m = 1u << bit;
        const unsigned hiMask = ~((m << 1) - 1u);
        const unsigned t = t_sh;
        unsigned local = 0;
        for (int i = tid; i < N; i += 256)
            if (((sv[i] ^ t) & hiMask) == 0 && !(sv[i] & m)) local++;
#pragma unroll
        for (int o = 16; o > 0; o >>= 1)
            local += __shfl_down_sync(0xffffffffu, local, o);
        if (lane == 0) wred[wid] = local;
        __syncthreads();
        if (tid == 0) {
            unsigned c = 0;
            for (int k = 0; k < 8; k++) c += wred[k];
            if (r_sh >= c) { t_sh |= m; r_sh -= c; }
        }
        __syncthreads();
    }

    if (tid == 0) tieCnt = 0;
    __syncthreads();
    const unsigned t = t_sh;
    for (int i = tid; i < N; i += 256)
        if (sv[i] == t) {
            unsigned p = atomicAdd(&tieCnt, 1u);
            if (p < 128) tieIdx[p] = (unsigned)i;
        }
    __syncthreads();
    if (tid == 0) {
        unsigned nt = tieCnt;
        if (nt > 128) nt = 128;
        for (unsigned i = 1; i < nt; i++) {
            unsigned v = tieIdx[i];
            int j = (int)i;
            while (j > 0 && tieIdx[j - 1] > v) { tieIdx[j] = tieIdx[j - 1]; j--; }
            tieIdx[j] = v;
        }
        unsigned r = r_sh;
        if (nt == 0) idx_sh = 0;
        else { if (r >= nt) r = nt - 1; idx_sh = tieIdx[r]; }
    }
    __syncthreads();
    const unsigned it = idx_sh;
    for (int i = tid; i < N; i += 256) {
        bool keep = (sv[i] > t) || (sv[i] == t && (unsigned)i >= it);
        wm[i] = keep ? w[i] : 0.0f;
    }
}

// ============================================================================
// Fused histogram+scan passes (last block scans). grid (G, count), block 1024.
// ============================================================================
__global__ __launch_bounds__(1024) void k_histscan1(MaskArgs a, int base) {
    int arr = base + blockIdx.y;
    const float* s = a.s[arr];
    int n = a.n[arr];
    unsigned* hist = g_hist5[arr];
    __shared__ unsigned wsum[32];
    __shared__ unsigned lastFlag;
    int tid = threadIdx.x;
    for (int i = blockIdx.x * 1024 + tid; i < n; i += gridDim.x * 1024) {
        unsigned b = __float_as_uint(fabsf(s[i]));
        atomicAdd(&hist[hperm(b >> 16)], 1u);
    }
    __threadfence();
    __syncthreads();
    if (tid == 0) {
        unsigned old = atomicAdd(&g_done[arr], 1u);
        lastFlag = (old == gridDim.x - 1) ? 1u : 0u;
        if (lastFlag) g_done[arr] = 0;
    }
    __syncthreads();
    if (!lastFlag) return;
    __threadfence();

    unsigned target = a.j[arr];
    int lane = tid & 31, wid = tid >> 5;
    unsigned local = 0;
#pragma unroll
    for (int k = 0; k < 64; k++) local += hist[k * 1024 + tid];
    unsigned inc = local;
#pragma unroll
    for (int o = 1; o < 32; o <<= 1) {
        unsigned y = __shfl_up_sync(0xffffffffu, inc, o);
        if (lane >= o) inc += y;
    }
    if (lane == 31) wsum[wid] = inc;
    __syncthreads();
    if (wid == 0) {
        unsigned v = wsum[lane];
        unsigned iv = v;
#pragma unroll
        for (int o = 1; o < 32; o <<= 1) {
            unsigned y = __shfl_up_sync(0xffffffffu, iv, o);
            if (lane >= o) iv += y;
        }
        wsum[lane] = iv - v;
    }
    __syncthreads();
    unsigned run = wsum[wid] + (inc - local);
#pragma unroll
    for (int k = 0; k < 64; k++) {
        unsigned h = hist[k * 1024 + tid];
        if (h && run <= target && target < run + h) {
            g_sel5[arr].b1 = (unsigned)(tid * 64 + k);
            g_sel5[arr].rank1 = target - run;
        }
        run += h;
        hist[k * 1024 + tid] = 0;
    }
}

__global__ __launch_bounds__(1024) void k_histscan2(MaskArgs a, int base) {
    int arr = base + blockIdx.y;
    const float* s = a.s[arr];
    int n = a.n[arr];
    unsigned* hist = g_hist5[arr];
    __shared__ unsigned wsum[32];
    __shared__ unsigned lastFlag;
    int tid = threadIdx.x;
    unsigned b1 = g_sel5[arr].b1;
    for (int i = blockIdx.x * 1024 + tid; i < n; i += gridDim.x * 1024) {
        unsigned b = __float_as_uint(fabsf(s[i]));
        if ((b >> 16) == b1) atomicAdd(&hist[hperm(b & 0xFFFFu)], 1u);
    }
    __threadfence();
    __syncthreads();
    if (tid == 0) {
        unsigned old = atomicAdd(&g_done[arr], 1u);
        lastFlag = (old == gridDim.x - 1) ? 1u : 0u;
        if (lastFlag) g_done[arr] = 0;
    }
    __syncthreads();
    if (!lastFlag) return;
    __threadfence();

    int lane = tid & 31, wid = tid >> 5;
    unsigned target = g_sel5[arr].rank1;
    unsigned local = 0;
#pragma unroll
    for (int k = 0; k < 64; k++) local += hist[k * 1024 + tid];
    unsigned inc = local;
#pragma unroll
    for (int o = 1; o < 32; o <<= 1) {
        unsigned y = __shfl_up_sync(0xffffffffu, inc, o);
        if (lane >= o) inc += y;
    }
    if (lane == 31) wsum[wid] = inc;
    __syncthreads();
    if (wid == 0) {
        unsigned v = wsum[lane];
        unsigned iv = v;
#pragma unroll
        for (int o = 1; o < 32; o <<= 1) {
            unsigned y = __shfl_up_sync(0xffffffffu, iv, o);
            if (lane >= o) iv += y;
        }
        wsum[lane] = iv - v;
    }
    __syncthreads();
    if (tid == 0) g_sel5[arr].tieCount = 0;
    unsigned run = wsum[wid] + (inc - local);
#pragma unroll
    for (int k = 0; k < 64; k++) {
        unsigned h = hist[k * 1024 + tid];
        if (h && run <= target && target < run + h) {
            g_sel5[arr].tbits = (g_sel5[arr].b1 << 16) | (unsigned)(tid * 64 + k);
            g_sel5[arr].r = target - run;
        }
        run += h;
        hist[k * 1024 + tid] = 0;
    }
}

__global__ void k_ties_all(MaskArgs a, int base) {
    int arr = base + blockIdx.y;
    const float* s = a.s[arr];
    int n = a.n[arr];
    unsigned t = g_sel5[arr].tbits;
    for (int i = blockIdx.x * blockDim.x + threadIdx.x; i < n;
         i += gridDim.x * blockDim.x) {
        unsigned b = __float_as_uint(fabsf(s[i]));
        if (b == t) {
            unsigned p = atomicAdd(&g_sel5[arr].tieCount, 1u);
            if (p < 2048) g_sel5[arr].tieIdx[p] = (unsigned)i;
        }
    }
    __syncthreads();
    if (threadIdx.x == 0) {
        __threadfence();
        unsigned old = atomicAdd(&g_done[arr], 1u);
        if (old == gridDim.x - 1) {
            __threadfence();
            g_done[arr] = 0;
            Sel& sel = g_sel5[arr];
            unsigned nt = sel.tieCount;
            if (nt > 2048) nt = 2048;
            for (unsigned i = 1; i < nt; i++) {
                unsigned v = sel.tieIdx[i];
                int j = (int)i;
                while (j > 0 && sel.tieIdx[j - 1] > v) {
                    sel.tieIdx[j] = sel.tieIdx[j - 1];
                    j--;
                }
                sel.tieIdx[j] = v;
            }
            unsigned r = sel.r;
            if (nt == 0) { sel.idxThresh = 0; return; }
            if (r >= nt) r = nt - 1;
            sel.idxThresh = sel.tieIdx[r];
        }
    }
}

__global__ void k_apply_all(MaskArgs a, int base) {
    int arr = base + blockIdx.y;
    const float* s = a.s[arr];
    const float* w = a.w[arr];
    float* wm = a.wm[arr];
    int n = a.n[arr];
    unsigned t = g_sel5[arr].tbits;
    unsigned it = g_sel5[arr].idxThresh;
    for (int i = blockIdx.x * blockDim.x + threadIdx.x; i < n;
         i += gridDim.x * blockDim.x) {
        unsigned b = __float_as_uint(fabsf(s[i]));
        bool keep = (b > t) || (b == t && (unsigned)i >= it);
        wm[i] = keep ? w[i] : 0.0f;
    }
}

// apply for a single conv array (sel index 1+y): masked fp16, [co][pos][ci].
__global__ void k_apply_conv(ConvApply ca, int y) {
    const float* s = ca.s[y];
    const float* w = ca.w[y];
    __half* dst = ca.dst[y];
    int n = ca.n[y];
    int cin = ca.cin[y];
    unsigned t = g_sel5[1 + y].tbits;
    unsigned it = g_sel5[1 + y].idxThresh;
    for (int i = blockIdx.x * blockDim.x + threadIdx.x; i < n;
         i += gridDim.x * blockDim.x) {
        unsigned b = __float_as_uint(fabsf(s[i]));
        bool keep = (b > t) || (b == t && (unsigned)i >= it);
        float v = keep ? w[i] : 0.0f;
        int p = i % 9;
        int ci = (i / 9) % cin;
        int co = i / (9 * cin);
        dst[((size_t)co * 9 + p) * cin + ci] = __float2half_rn(v);
    }
}

// ============================================================================
// conv1 via HMMA implicit GEMM: K=27 (pad 32), M=128 px, N=128 co.
// Block 256 (8 warps); one staging phase, 16 MMAs total.
// ============================================================================
__global__ __launch_bounds__(256) void k_conv1_mma(
    const float* __restrict__ x, const float* __restrict__ wm1,
    const float* __restrict__ bias, __half* __restrict__ outH) {
    extern __shared__ char smem[];
    float* s_bias = (float*)smem;
    const uint32_t sbase = smem_u32(smem);
    const uint32_t TA = sbase + 1024;          // A: 128 rows x 128B (K pad 64)
    const uint32_t TBB = TA + 16384;           // B: 128 rows x 128B
    __half* sAh = (__half*)(smem + 1024);
    __half* sBh = (__half*)(smem + 1024 + 16384);

    const int tid = threadIdx.x;
    const int warp = tid >> 5, ln = tid & 31;
    const int mtile = blockIdx.x, n = blockIdx.z;
    const int oy0 = (mtile >> 2) * 8;          // 8 y-tiles
    const int ox0 = (mtile & 3) * 16;          // 4 x-tiles

    if (tid < 128) s_bias[tid] = bias[tid];

    // stage A: row = px (ty*16+tx), k = cc*9 + ky*3 + kx (27 used, 32 padded)
    for (int idx = tid; idx < 128 * 32; idx += 256) {
        int row = idx >> 5, k = idx & 31;
        float v = 0.0f;
        if (k < 27) {
            int cc = k / 9, rem = k - cc * 9;
            int ky = rem / 3, kx = rem - ky * 3;
            int Y = oy0 + (row >> 4) + ky - 1;
            int X = ox0 + (row & 15) + kx - 1;
            if (Y >= 0 && Y < 64 && X >= 0 && X < 64)
                v = x[(((size_t)n * 3 + cc) * 64 + Y) * 64 + X];
        }
        *(__half*)((char*)sAh + SWZ((uint32_t)(row * 128 + k * 2))) =
            __float2half_rn(v);
    }
    // stage B: row = co, k same ordering (w1 is [co][cc][ky][kx] = co*27+k)
    for (int idx = tid; idx < 128 * 32; idx += 256) {
        int row = idx >> 5, k = idx & 31;
        float v = (k < 27) ? wm1[row * 27 + k] : 0.0f;
        *(__half*)((char*)sBh + SWZ((uint32_t)(row * 128 + k * 2))) =
            __float2half_rn(v);
    }
    __syncthreads();

    const int wm = (warp & 3) * 32;
    const int wn = (warp >> 2) * 64;
    const int lrow = (ln & 7) + ((ln >> 3) & 1) * 8;
    const int lkb = ((ln >> 4) & 1) * 16;

    float d[2][8][4];
#pragma unroll
    for (int mi = 0; mi < 2; mi++)
#pragma unroll
        for (int nj = 0; nj < 8; nj++)
#pragma unroll
            for (int q = 0; q < 4; q++) d[mi][nj][q] = 0.0f;

#pragma unroll
    for (int ks = 0; ks < 2; ks++) {
        uint32_t a[2][4];
#pragma unroll
        for (int mi = 0; mi < 2; mi++)
            ldsm4(a[mi], TA + SWZ((uint32_t)((wm + mi * 16 + lrow) * 128 +
                                             ks * 32 + lkb)));
#pragma unroll
        for (int nj2 = 0; nj2 < 4; nj2++) {
            uint32_t b[4];
            ldsm4(b, TBB + SWZ((uint32_t)((wn + nj2 * 16 + lrow) * 128 +
                                          ks * 32 + lkb)));
#pragma unroll
            for (int mi = 0; mi < 2; mi++) {
                mma16816(d[mi][nj2 * 2], a[mi], b[0], b[2]);
                mma16816(d[mi][nj2 * 2 + 1], a[mi], b[1], b[3]);
            }
        }
    }

    // epilogue: bias + relu, NHWC fp16
#pragma unroll
    for (int mi = 0; mi < 2; mi++) {
#pragma unroll
        for (int half = 0; half < 2; half++) {
            int r = wm + mi * 16 + half * 8 + (ln >> 2);
            int oy = oy0 + (r >> 4), ox = ox0 + (r & 15);
            size_t base = (((size_t)n * 64 + oy) * 64 + ox) * 128;
#pragma unroll
            for (int nj = 0; nj < 8; nj++) {
                int col = wn + nj * 8 + (ln & 3) * 2;
                float v0 = d[mi][nj][half * 2 + 0] + s_bias[col];
                float v1 = d[mi][nj][half * 2 + 1] + s_bias[col + 1];
                v0 = v0 > 0.0f ? v0 : 0.0f;
                v1 = v1 > 0.0f ? v1 : 0.0f;
                *(__half2*)(outH + base + col) = __floats2half2_rn(v0, v1);
            }
        }
    }
}

// ============================================================================
// HMMA implicit-GEMM conv (stride 2): unchanged from round 12 — proven.
// ============================================================================
template <int CIN, int HOUT, int WOUT, int COUT, int OUTMODE>
__global__ __launch_bounds__(256, 2) void k_conv_mma(
    const __half* __restrict__ in, const __half* __restrict__ wH,
    const float* __restrict__ bias, __half* __restrict__ outH,
    float* __restrict__ pool) {
    constexpr int HIN = 2 * HOUT, WIN = 2 * WOUT;
    constexpr int NCH = CIN / 64;
    constexpr int ST = 9 * NCH;
    constexpr int BUF = 32768;

    extern __shared__ char smem[];
    float* s_bias = (float*)smem;
    float* s_red = (float*)(smem + 512);
    const uint32_t sbase = smem_u32(smem);
    const uint32_t TB = sbase + 4096;

    const int tid = threadIdx.x;
    const int warp = tid >> 5, ln = tid & 31;
    const int mtile = blockIdx.x, cob = blockIdx.y, n = blockIdx.z;
    const int oy0 = (mtile / (WOUT / 16)) * 8;
    const int ox0 = (mtile % (WOUT / 16)) * 16;
    const int co0 = cob * 128;

    if (tid < 128) s_bias[tid] = bias[co0 + tid];

    const int wm = (warp & 3) * 32;
    const int wn = (warp >> 2) * 64;
    const int lrow = (ln & 7) + ((ln >> 3) & 1) * 8;
    const int lkb = ((ln >> 4) & 1) * 16;

    float d[2][8][4];
#pragma unroll
    for (int mi = 0; mi < 2; mi++)
#pragma unroll
        for (int nj = 0; nj < 8; nj++)
#pragma unroll
            for (int q = 0; q < 4; q++) d[mi][nj][q] = 0.0f;

    auto stage_load = [&](int s) {
        const int buf = s & 1;
        const int p = s / NCH, q = s - p * NCH;
        const int ky = p / 3, kx = p - ky * 3;
        const int c0 = q * 64;
        const uint32_t tb = TB + buf * BUF;
        for (int seg = tid; seg < 1024; seg += 256) {
            int row = seg >> 3, j = seg & 7;
            int ty = row >> 4, tx = row & 15;
            int Y = 2 * (oy0 + ty) + ky - 1;
            int X = 2 * (ox0 + tx) + kx - 1;
            bool inb = (Y >= 0 && Y < HIN && X >= 0 && X < WIN);
            const void* src = in +
                ((((size_t)n * HIN + (inb ? Y : 0)) * WIN + (inb ? X : 0)) * CIN +
                 c0 + j * 8);
            cp_async16(tb + SWZ((uint32_t)(row * 128 + j * 16)), src, inb);
        }
        for (int seg = tid; seg < 1024; seg += 256) {
            int row = seg >> 3, j = seg & 7;
            const void* src =
                wH + (((size_t)(co0 + row) * 9 + p) * CIN + c0 + j * 8);
            cp_async16(tb + 16384 + SWZ((uint32_t)(row * 128 + j * 16)), src, true);
        }
        cp_commit();
    };

    stage_load(0);
    for (int s = 0; s < ST; s++) {
        if (s + 1 < ST) {
            stage_load(s + 1);
            asm volatile("cp.async.wait_group 1;" ::: "memory");
        } else {
            asm volatile("cp.async.wait_group 0;" ::: "memory");
        }
        __syncthreads();

        const uint32_t tb = TB + (s & 1) * BUF;
        const uint32_t bb = tb + 16384;
#pragma unroll
        for (int ks = 0; ks < 4; ks++) {
            uint32_t a[2][4];
#pragma unroll
            for (int mi = 0; mi < 2; mi++)
                ldsm4(a[mi], tb + SWZ((uint32_t)((wm + mi * 16 + lrow) * 128 +
                                                 ks * 32 + lkb)));
#pragma unroll
            for (int nj2 = 0; nj2 < 4; nj2++) {
                uint32_t b[4];
                ldsm4(b, bb + SWZ((uint32_t)((wn + nj2 * 16 + lrow) * 128 +
                                             ks * 32 + lkb)));
#pragma unroll
                for (int mi = 0; mi < 2; mi++) {
                    mma16816(d[mi][nj2 * 2], a[mi], b[0], b[2]);
                    mma16816(d[mi][nj2 * 2 + 1], a[mi], b[1], b[3]);
                }
            }
        }
        __syncthreads();
    }

    if (OUTMODE == 0) {
#pragma unroll
        for (int mi = 0; mi < 2; mi++) {
#pragma unroll
            for (int half = 0; half < 2; half++) {
                int r = wm + mi * 16 + half * 8 + (ln >> 2);
                int oy = oy0 + (r >> 4), ox = ox0 + (r & 15);
                size_t base = (((size_t)n * HOUT + oy) * WOUT + ox) * COUT + co0;
#pragma unroll
                for (int nj = 0; nj < 8; nj++) {
                    int col = wn + nj * 8 + (ln & 3) * 2;
                    float v0 = d[mi][nj][half * 2 + 0] + s_bias[col];
                    float v1 = d[mi][nj][half * 2 + 1] + s_bias[col + 1];
                    v0 = v0 > 0.0f ? v0 : 0.0f;
                    v1 = v1 > 0.0f ? v1 : 0.0f;
                    *(__half2*)(outH + base + col) = __floats2half2_rn(v0, v1);
                }
            }
        }
    } else {
        float sv[16];
#pragma unroll
        for (int nj = 0; nj < 8; nj++) {
            int col0 = wn + nj * 8 + (ln & 3) * 2;
            float b0 = s_bias[col0], b1 = s_bias[col0 + 1];
            float s0 = 0.0f, s1 = 0.0f;
#pragma unroll
            for (int mi = 0; mi < 2; mi++)
#pragma unroll
                for (int half = 0; half < 2; half++) {
                    float v0 = d[mi][nj][half * 2 + 0] + b0;
                    float v1 = d[mi][nj][half * 2 + 1] + b1;
                    s0 += v0 > 0.0f ? v0 : 0.0f;
                    s1 += v1 > 0.0f ? v1 : 0.0f;
                }
            sv[nj * 2] = s0;
            sv[nj * 2 + 1] = s1;
        }
#pragma unroll
        for (int off = 4; off < 32; off <<= 1)
#pragma unroll
            for (int k = 0; k < 16; k++)
                sv[k] += __shfl_xor_sync(0xffffffffu, sv[k], off);
        if (ln < 4) {
#pragma unroll
            for (int nj = 0; nj < 8; nj++) {
                s_red[warp * 64 + nj * 8 + ln * 2 + 0] = sv[nj * 2];
                s_red[warp * 64 + nj * 8 + ln * 2 + 1] = sv[nj * 2 + 1];
            }
        }
        __syncthreads();
        if (tid < 128) {
            int col = tid;
            int g = col >> 6, r = col & 63;
            float t = s_red[(g * 4 + 0) * 64 + r] + s_red[(g * 4 + 1) * 64 + r] +
                      s_red[(g * 4 + 2) * 64 + r] + s_red[(g * 4 + 3) * 64 + r];
            atomicAdd(&pool[n * 512 + co0 + col], t * (1.0f / 256.0f));
        }
    }
}

// ============================================================================
// FC1 (coalesced): warp per output. grid (128, 64), block 256.
// ============================================================================
__global__ void k_fc1(const float* __restrict__ pool, const float* __restrict__ w,
                      const float* __restrict__ b, float* __restrict__ out) {
    int n = blockIdx.y;
    __shared__ float sp[512];
    int tid = threadIdx.x;
    for (int k = tid; k < 512; k += 256) sp[k] = pool[n * 512 + k];
    __syncthreads();
    int warp = tid >> 5, ln = tid & 31;
    int o = blockIdx.x * 8 + warp;
    const float* wp = w + (size_t)o * 512;
    float acc = 0.0f;
#pragma unroll
    for (int k = ln; k < 512; k += 32) acc = fmaf(sp[k], wp[k], acc);
#pragma unroll
    for (int off = 16; off > 0; off >>= 1)
        acc += __shfl_down_sync(0xffffffffu, acc, off);
    if (ln == 0) {
        float v = acc + b[o];
        out[n * 1024 + o] = v > 0.0f ? v : 0.0f;
    }
}

// ============================================================================
// FC2: grid 64, block 320 (warp per output).
// ============================================================================
__global__ void k_fc2(const float* __restrict__ a, const float* __restrict__ w,
                      const float* __restrict__ b, float* __restrict__ out) {
    int n = blockIdx.x;
    int o = threadIdx.x >> 5, lane = threadIdx.x & 31;
    float acc = 0.0f;
    const float* ap = a + (size_t)n * 1024;
    const float* wp = w + (size_t)o * 1024;
    for (int k = lane; k < 1024; k += 32) acc = fmaf(ap[k], wp[k], acc);
#pragma unroll
    for (int off = 16; off > 0; off >>= 1)
        acc += __shfl_down_sync(0xffffffffu, acc, off);
    if (lane == 0) out[n * 10 + o] = acc + b[o];
}

// ============================================================================
// Host side
// ============================================================================
extern "C" void kernel_launch(void* const* d_in, const int* in_sizes, int n_in,
                              void* d_out, int out_size) {
    (void)in_sizes; (void)n_in; (void)out_size;
    const float* x   = (const float*)d_in[0];
    const float* w1  = (const float*)d_in[1];
    const float* s1  = (const float*)d_in[2];
    const float* b1  = (const float*)d_in[3];
    const float* w2  = (const float*)d_in[4];
    const float* s2  = (const float*)d_in[5];
    const float* b2  = (const float*)d_in[6];
    const float* w3  = (const float*)d_in[7];
    const float* s3  = (const float*)d_in[8];
    const float* b3  = (const float*)d_in[9];
    const float* fw1 = (const float*)d_in[10];
    const float* fs1 = (const float*)d_in[11];
    const float* fb1 = (const float*)d_in[12];
    const float* fw2 = (const float*)d_in[13];
    const float* fs2 = (const float*)d_in[14];
    const float* fb2 = (const float*)d_in[15];
    float* out = (float*)d_out;

    float *wm1, *fwm1, *fwm2, *pool, *a1;
    __half *w2h, *w3h, *h1, *h2;
    cudaGetSymbolAddress((void**)&wm1, g_wm1);
    cudaGetSymbolAddress((void**)&fwm1, g_fwm1);
    cudaGetSymbolAddress((void**)&fwm2, g_fwm2);
    cudaGetSymbolAddress((void**)&w2h, g_w2h);
    cudaGetSymbolAddress((void**)&w3h, g_w3h);
    cudaGetSymbolAddress((void**)&h1, g_h1);
    cudaGetSymbolAddress((void**)&h2, g_h2);
    cudaGetSymbolAddress((void**)&pool, g_pool);
    cudaGetSymbolAddress((void**)&a1, g_a1);

    auto c2 = k_conv_mma<128, 32, 32, 256, 0>;
    auto c3 = k_conv_mma<256, 16, 16, 512, 1>;
    const int mma_smem = 4096 + 2 * 32768;  // 69632
    cudaFuncSetAttribute((const void*)c2, cudaFuncAttributeMaxDynamicSharedMemorySize, mma_smem);
    cudaFuncSetAttribute((const void*)c3, cudaFuncAttributeMaxDynamicSharedMemorySize, mma_smem);
    const int c1_smem = 1024 + 2 * 16384;   // 33792 (<48K, no attr needed)

    MaskArgs ma;
    ma.s[0] = s1;  ma.w[0] = w1;  ma.wm[0] = wm1;     ma.n[0] = 3456;    ma.j[0] = 1728u;
    ma.s[1] = s2;  ma.w[1] = w2;  ma.wm[1] = nullptr; ma.n[1] = 294912;  ma.j[1] = 147456u;
    ma.s[2] = s3;  ma.w[2] = w3;  ma.wm[2] = nullptr; ma.n[2] = 1179648; ma.j[2] = 589824u;
    ma.s[3] = fs1; ma.w[3] = fw1; ma.wm[3] = fwm1;    ma.n[3] = 524288;  ma.j[3] = 262144u;
    ma.s[4] = fs2; ma.w[4] = fw2; ma.wm[4] = fwm2;    ma.n[4] = 10240;   ma.j[4] = 5120u;

    ConvApply ca;
    ca.s[0] = s2; ca.w[0] = w2; ca.dst[0] = w2h; ca.n[0] = 294912;  ca.cin[0] = 128;
    ca.s[1] = s3; ca.w[1] = w3; ca.dst[1] = w3h; ca.n[1] = 1179648; ca.cin[1] = 256;

    cudaStream_t sA = g_res.sA, sB = g_res.sB;

    // ---- fork ----
    cudaEventRecord(g_res.evStart, 0);

    // main: pool memset + conv1 mask + conv1 (MMA)
    cudaMemsetAsync(pool, 0, 64 * 512 * sizeof(float));
    k_mask0<<<1, 256>>>(s1, w1, wm1);
    k_conv1_mma<<<dim3(32, 1, 64), 256, c1_smem>>>(x, wm1, b1, h1);

    // side A: w2 mask -> evW2, then w3 mask -> evW3
    cudaStreamWaitEvent(sA, g_res.evStart, 0);
    k_histscan1<<<dim3(40, 1), 1024, 0, sA>>>(ma, 1);
    k_histscan2<<<dim3(40, 1), 1024, 0, sA>>>(ma, 1);
    k_ties_all<<<dim3(160, 1), 256, 0, sA>>>(ma, 1);
    k_apply_conv<<<160, 256, 0, sA>>>(ca, 0);
    cudaEventRecord(g_res.evW2, sA);
    k_histscan1<<<dim3(40, 1), 1024, 0, sA>>>(ma, 2);
    k_histscan2<<<dim3(40, 1), 1024, 0, sA>>>(ma, 2);
    k_ties_all<<<dim3(160, 1), 256, 0, sA>>>(ma, 2);
    k_apply_conv<<<160, 256, 0, sA>>>(ca, 1);
    cudaEventRecord(g_res.evW3, sA);

    // side B: FC masks (arrays 3,4)
    cudaStreamWaitEvent(sB, g_res.evStart, 0);
    k_histscan1<<<dim3(40, 2), 1024, 0, sB>>>(ma, 3);
    k_histscan2<<<dim3(40, 2), 1024, 0, sB>>>(ma, 3);
    k_ties_all<<<dim3(160, 2), 256, 0, sB>>>(ma, 3);
    k_apply_all<<<dim3(160, 2), 256, 0, sB>>>(ma, 3);
    cudaEventRecord(g_res.evFC, sB);

    // main: conv2 after w2h (conv1 already ordered on main stream)
    cudaStreamWaitEvent(0, g_res.evW2, 0);
    c2<<<dim3(8, 2, 64), 256, mma_smem>>>(h1, w2h, b2, h2, nullptr);
    cudaStreamWaitEvent(0, g_res.evW3, 0);
    c3<<<dim3(2, 4, 64), 256, mma_smem>>>(h2, w3h, b3, nullptr, pool);

    // head
    cudaStreamWaitEvent(0, g_res.evFC, 0);
    k_fc1<<<dim3(128, 64), 256>>>(pool, fwm1, fb1, a1);
    k_fc2<<<64, 320>>>(a1, fwm2, fb2, out);
}

// round 14
// speedup vs baseline: 1.0478x; 1.0478x over previous
#include <cuda_runtime.h>
#include <cuda_fp16.h>
#include <cstdint>

// ============================================================================
// Device scratch
// ============================================================================
__device__ float g_wm1[3456];
__device__ float g_fwm1[524288];
__device__ float g_fwm2[10240];

__device__ __align__(16) __half g_w2h[294912];
__device__ __align__(16) __half g_w3h[1179648];

__device__ __align__(16) __half g_h1[64u*64u*64u*128u];
__device__ __align__(16) __half g_h2[64u*32u*32u*256u];
__device__ float g_pool[64 * 512];
__device__ float g_a1[64 * 1024];

__device__ unsigned g_hist5[5][65536];
__device__ unsigned g_done[5];
struct Sel {
    unsigned b1, rank1, tbits, r, tieCount, idxThresh;
    unsigned tieIdx[2048];
};
__device__ Sel g_sel5[5];

struct MaskArgs {
    const float* s[5];
    const float* w[5];
    float* wm[5];
    int n[5];
    unsigned j[5];
};
struct ConvApply {
    const float* s[2];
    const float* w[2];
    __half* dst[2];
    int n[2];
    int cin[2];
};

__device__ __forceinline__ unsigned hperm(unsigned v) {
    return (v & 63u) * 1024u + (v >> 6);
}

// ============================================================================
// Persistent streams/events
// ============================================================================
struct GpuRes {
    cudaStream_t sA;
    cudaEvent_t evStart, evC1;
    GpuRes() {
        cudaStreamCreateWithFlags(&sA, cudaStreamNonBlocking);
        cudaEventCreateWithFlags(&evStart, cudaEventDisableTiming);
        cudaEventCreateWithFlags(&evC1, cudaEventDisableTiming);
    }
};
static GpuRes g_res;

// ============================================================================
// PTX helpers
// ============================================================================
#define SWZ(o) ((o) ^ (((o) >> 3) & 0x70))

__device__ __forceinline__ uint32_t smem_u32(const void* p) {
    uint32_t a;
    asm("{ .reg .u64 t; cvta.to.shared.u64 t, %1; cvt.u32.u64 %0, t; }"
        : "=r"(a) : "l"(p));
    return a;
}
__device__ __forceinline__ void cp_async16(uint32_t dst, const void* src, bool inb) {
    int sz = inb ? 16 : 0;
    asm volatile("cp.async.cg.shared.global [%0], [%1], 16, %2;\n"
                 :: "r"(dst), "l"(src), "r"(sz));
}
__device__ __forceinline__ void cp_commit() {
    asm volatile("cp.async.commit_group;\n" ::: "memory");
}
__device__ __forceinline__ void ldsm4(uint32_t* r, uint32_t addr) {
    asm volatile("ldmatrix.sync.aligned.m8n8.x4.shared.b16 {%0,%1,%2,%3}, [%4];"
                 : "=r"(r[0]), "=r"(r[1]), "=r"(r[2]), "=r"(r[3]) : "r"(addr));
}
__device__ __forceinline__ void mma16816(float* d, const uint32_t* a,
                                         uint32_t b0, uint32_t b1) {
    asm volatile(
        "mma.sync.aligned.m16n8k16.row.col.f32.f16.f16.f32 "
        "{%0,%1,%2,%3}, {%4,%5,%6,%7}, {%8,%9}, {%0,%1,%2,%3};"
        : "+f"(d[0]), "+f"(d[1]), "+f"(d[2]), "+f"(d[3])
        : "r"(a[0]), "r"(a[1]), "r"(a[2]), "r"(a[3]), "r"(b0), "r"(b1));
}

// ============================================================================
// k_mask0: exact select+apply for conv1 scores (n=3456, j=1728), 1 block.
// ============================================================================
__global__ __launch_bounds__(256) void k_mask0(const float* __restrict__ s,
                                               const float* __restrict__ w,
                                               float* __restrict__ wm) {
    constexpr int N = 3456;
    constexpr unsigned J = 1728;
    __shared__ unsigned sv[N];
    __shared__ unsigned wred[8];
    __shared__ unsigned t_sh, r_sh, tieCnt, idx_sh;
    __shared__ unsigned tieIdx[128];
    const int tid = threadIdx.x;
    const int lane = tid & 31, wid = tid >> 5;

    for (int i = tid; i < N; i += 256) sv[i] = __float_as_uint(fabsf(s[i]));
    if (tid == 0) { t_sh = 0; r_sh = J; }
    __syncthreads();

    for (int bit = 31; bit >= 0; bit--) {
        const unsigned m = 1u << bit;
        const unsigned hiMask = ~((m << 1) - 1u);
        const unsigned t = t_sh;
        unsigned local = 0;
        for (int i = tid; i < N; i += 256)
            if (((sv[i] ^ t) & hiMask) == 0 && !(sv[i] & m)) local++;
#pragma unroll
        for (int o = 16; o > 0; o >>= 1)
            local += __shfl_down_sync(0xffffffffu, local, o);
        if (lane == 0) wred[wid] = local;
        __syncthreads();
        if (tid == 0) {
            unsigned c = 0;
            for (int k = 0; k < 8; k++) c += wred[k];
            if (r_sh >= c) { t_sh |= m; r_sh -= c; }
        }
        __syncthreads();
    }

    if (tid == 0) tieCnt = 0;
    __syncthreads();
    const unsigned t = t_sh;
    for (int i = tid; i < N; i += 256)
        if (sv[i] == t) {
            unsigned p = atomicAdd(&tieCnt, 1u);
            if (p < 128) tieIdx[p] = (unsigned)i;
        }
    __syncthreads();
    if (tid == 0) {
        unsigned nt = tieCnt;
        if (nt > 128) nt = 128;
        for (unsigned i = 1; i < nt; i++) {
            unsigned v = tieIdx[i];
            int j = (int)i;
            while (j > 0 && tieIdx[j - 1] > v) { tieIdx[j] = tieIdx[j - 1]; j--; }
            tieIdx[j] = v;
        }
        unsigned r = r_sh;
        if (nt == 0) idx_sh = 0;
        else { if (r >= nt) r = nt - 1; idx_sh = tieIdx[r]; }
    }
    __syncthreads();
    const unsigned it = idx_sh;
    for (int i = tid; i < N; i += 256) {
        bool keep = (sv[i] > t) || (sv[i] == t && (unsigned)i >= it);
        wm[i] = keep ? w[i] : 0.0f;
    }
}

// ============================================================================
// Fused histogram+scan passes (last block scans). grid (G, 4), block 1024.
// Arrays 1..4 (w2, w3, fs1, fs2).
// ============================================================================
__global__ __launch_bounds__(1024) void k_histscan1(MaskArgs a) {
    int arr = 1 + blockIdx.y;
    const float* s = a.s[arr];
    int n = a.n[arr];
    unsigned* hist = g_hist5[arr];
    __shared__ unsigned wsum[32];
    __shared__ unsigned lastFlag;
    int tid = threadIdx.x;
    for (int i = blockIdx.x * 1024 + tid; i < n; i += gridDim.x * 1024) {
        unsigned b = __float_as_uint(fabsf(s[i]));
        atomicAdd(&hist[hperm(b >> 16)], 1u);
    }
    __threadfence();
    __syncthreads();
    if (tid == 0) {
        unsigned old = atomicAdd(&g_done[arr], 1u);
        lastFlag = (old == gridDim.x - 1) ? 1u : 0u;
        if (lastFlag) g_done[arr] = 0;
    }
    __syncthreads();
    if (!lastFlag) return;
    __threadfence();

    unsigned target = a.j[arr];
    int lane = tid & 31, wid = tid >> 5;
    unsigned local = 0;
#pragma unroll
    for (int k = 0; k < 64; k++) local += hist[k * 1024 + tid];
    unsigned inc = local;
#pragma unroll
    for (int o = 1; o < 32; o <<= 1) {
        unsigned y = __shfl_up_sync(0xffffffffu, inc, o);
        if (lane >= o) inc += y;
    }
    if (lane == 31) wsum[wid] = inc;
    __syncthreads();
    if (wid == 0) {
        unsigned v = wsum[lane];
        unsigned iv = v;
#pragma unroll
        for (int o = 1; o < 32; o <<= 1) {
            unsigned y = __shfl_up_sync(0xffffffffu, iv, o);
            if (lane >= o) iv += y;
        }
        wsum[lane] = iv - v;
    }
    __syncthreads();
    unsigned run = wsum[wid] + (inc - local);
#pragma unroll
    for (int k = 0; k < 64; k++) {
        unsigned h = hist[k * 1024 + tid];
        if (h && run <= target && target < run + h) {
            g_sel5[arr].b1 = (unsigned)(tid * 64 + k);
            g_sel5[arr].rank1 = target - run;
        }
        run += h;
        hist[k * 1024 + tid] = 0;
    }
}

__global__ __launch_bounds__(1024) void k_histscan2(MaskArgs a) {
    int arr = 1 + blockIdx.y;
    const float* s = a.s[arr];
    int n = a.n[arr];
    unsigned* hist = g_hist5[arr];
    __shared__ unsigned wsum[32];
    __shared__ unsigned lastFlag;
    int tid = threadIdx.x;
    unsigned b1 = g_sel5[arr].b1;
    for (int i = blockIdx.x * 1024 + tid; i < n; i += gridDim.x * 1024) {
        unsigned b = __float_as_uint(fabsf(s[i]));
        if ((b >> 16) == b1) atomicAdd(&hist[hperm(b & 0xFFFFu)], 1u);
    }
    __threadfence();
    __syncthreads();
    if (tid == 0) {
        unsigned old = atomicAdd(&g_done[arr], 1u);
        lastFlag = (old == gridDim.x - 1) ? 1u : 0u;
        if (lastFlag) g_done[arr] = 0;
    }
    __syncthreads();
    if (!lastFlag) return;
    __threadfence();

    int lane = tid & 31, wid = tid >> 5;
    unsigned target = g_sel5[arr].rank1;
    unsigned local = 0;
#pragma unroll
    for (int k = 0; k < 64; k++) local += hist[k * 1024 + tid];
    unsigned inc = local;
#pragma unroll
    for (int o = 1; o < 32; o <<= 1) {
        unsigned y = __shfl_up_sync(0xffffffffu, inc, o);
        if (lane >= o) inc += y;
    }
    if (lane == 31) wsum[wid] = inc;
    __syncthreads();
    if (wid == 0) {
        unsigned v = wsum[lane];
        unsigned iv = v;
#pragma unroll
        for (int o = 1; o < 32; o <<= 1) {
            unsigned y = __shfl_up_sync(0xffffffffu, iv, o);
            if (lane >= o) iv += y;
        }
        wsum[lane] = iv - v;
    }
    __syncthreads();
    if (tid == 0) g_sel5[arr].tieCount = 0;
    unsigned run = wsum[wid] + (inc - local);
#pragma unroll
    for (int k = 0; k < 64; k++) {
        unsigned h = hist[k * 1024 + tid];
        if (h && run <= target && target < run + h) {
            g_sel5[arr].tbits = (g_sel5[arr].b1 << 16) | (unsigned)(tid * 64 + k);
            g_sel5[arr].r = target - run;
        }
        run += h;
        hist[k * 1024 + tid] = 0;
    }
}

// ============================================================================
// Merged ties+apply: one pass. b>t keep, b<t drop, b==t tentatively drop and
// record index (fixed by k_fixup). Conv arrays (y<2) write fp16 [co][pos][ci];
// FC arrays write fp32 flat. grid (G, 4), block 256.
// ============================================================================
__global__ void k_tieapply(MaskArgs a, ConvApply ca) {
    int y = blockIdx.y;
    int arr = 1 + y;
    const float* s = a.s[arr];
    const float* w = a.w[arr];
    int n = a.n[arr];
    unsigned t = g_sel5[arr].tbits;
    if (y < 2) {
        __half* dst = ca.dst[y];
        int cin = ca.cin[y];
        for (int i = blockIdx.x * blockDim.x + threadIdx.x; i < n;
             i += gridDim.x * blockDim.x) {
            unsigned b = __float_as_uint(fabsf(s[i]));
            if (b == t) {
                unsigned p = atomicAdd(&g_sel5[arr].tieCount, 1u);
                if (p < 2048) g_sel5[arr].tieIdx[p] = (unsigned)i;
            }
            float v = (b > t) ? w[i] : 0.0f;
            int p9 = i % 9;
            int ci = (i / 9) % cin;
            int co = i / (9 * cin);
            dst[((size_t)co * 9 + p9) * cin + ci] = __float2half_rn(v);
        }
    } else {
        float* wm = a.wm[arr];
        for (int i = blockIdx.x * blockDim.x + threadIdx.x; i < n;
             i += gridDim.x * blockDim.x) {
            unsigned b = __float_as_uint(fabsf(s[i]));
            if (b == t) {
                unsigned p = atomicAdd(&g_sel5[arr].tieCount, 1u);
                if (p < 2048) g_sel5[arr].tieIdx[p] = (unsigned)i;
            }
            wm[i] = (b > t) ? w[i] : 0.0f;
        }
    }
}

// Fix the tie elements: sort indices, keep sorted positions >= r. grid 4.
__global__ void k_fixup(MaskArgs a, ConvApply ca) {
    int y = blockIdx.x;
    int arr = 1 + y;
    if (threadIdx.x != 0) return;
    Sel& sel = g_sel5[arr];
    unsigned nt = sel.tieCount;
    if (nt > 2048) nt = 2048;
    if (nt == 0) return;
    for (unsigned i = 1; i < nt; i++) {
        unsigned v = sel.tieIdx[i];
        int j = (int)i;
        while (j > 0 && sel.tieIdx[j - 1] > v) {
            sel.tieIdx[j] = sel.tieIdx[j - 1];
            j--;
        }
        sel.tieIdx[j] = v;
    }
    unsigned r = sel.r;
    if (r >= nt) r = nt - 1;  // mirror prior clamp behavior
    const float* w = a.w[arr];
    for (unsigned k = r; k < nt; k++) {
        unsigned i = sel.tieIdx[k];
        float v = w[i];
        if (y < 2) {
            int cin = ca.cin[y];
            int p9 = i % 9;
            int ci = (i / 9) % cin;
            int co = i / (9 * cin);
            ca.dst[y][((size_t)co * 9 + p9) * cin + ci] = __float2half_rn(v);
        } else {
            a.wm[arr][i] = v;
        }
    }
}

// ============================================================================
// conv1 via HMMA implicit GEMM: K=27 (pad 32), M=128 px, N=128 co.
// ============================================================================
__global__ __launch_bounds__(256) void k_conv1_mma(
    const float* __restrict__ x, const float* __restrict__ wm1,
    const float* __restrict__ bias, __half* __restrict__ outH) {
    extern __shared__ char smem[];
    float* s_bias = (float*)smem;
    const uint32_t sbase = smem_u32(smem);
    const uint32_t TA = sbase + 1024;
    const uint32_t TBB = TA + 16384;
    __half* sAh = (__half*)(smem + 1024);
    __half* sBh = (__half*)(smem + 1024 + 16384);

    const int tid = threadIdx.x;
    const int warp = tid >> 5, ln = tid & 31;
    const int mtile = blockIdx.x, n = blockIdx.z;
    const int oy0 = (mtile >> 2) * 8;
    const int ox0 = (mtile & 3) * 16;

    if (tid < 128) s_bias[tid] = bias[tid];

    for (int idx = tid; idx < 128 * 32; idx += 256) {
        int row = idx >> 5, k = idx & 31;
        float v = 0.0f;
        if (k < 27) {
            int cc = k / 9, rem = k - cc * 9;
            int ky = rem / 3, kx = rem - ky * 3;
            int Y = oy0 + (row >> 4) + ky - 1;
            int X = ox0 + (row & 15) + kx - 1;
            if (Y >= 0 && Y < 64 && X >= 0 && X < 64)
                v = x[(((size_t)n * 3 + cc) * 64 + Y) * 64 + X];
        }
        *(__half*)((char*)sAh + SWZ((uint32_t)(row * 128 + k * 2))) =
            __float2half_rn(v);
    }
    for (int idx = tid; idx < 128 * 32; idx += 256) {
        int row = idx >> 5, k = idx & 31;
        float v = (k < 27) ? wm1[row * 27 + k] : 0.0f;
        *(__half*)((char*)sBh + SWZ((uint32_t)(row * 128 + k * 2))) =
            __float2half_rn(v);
    }
    __syncthreads();

    const int wm = (warp & 3) * 32;
    const int wn = (warp >> 2) * 64;
    const int lrow = (ln & 7) + ((ln >> 3) & 1) * 8;
    const int lkb = ((ln >> 4) & 1) * 16;

    float d[2][8][4];
#pragma unroll
    for (int mi = 0; mi < 2; mi++)
#pragma unroll
        for (int nj = 0; nj < 8; nj++)
#pragma unroll
            for (int q = 0; q < 4; q++) d[mi][nj][q] = 0.0f;

#pragma unroll
    for (int ks = 0; ks < 2; ks++) {
        uint32_t a[2][4];
#pragma unroll
        for (int mi = 0; mi < 2; mi++)
            ldsm4(a[mi], TA + SWZ((uint32_t)((wm + mi * 16 + lrow) * 128 +
                                             ks * 32 + lkb)));
#pragma unroll
        for (int nj2 = 0; nj2 < 4; nj2++) {
            uint32_t b[4];
            ldsm4(b, TBB + SWZ((uint32_t)((wn + nj2 * 16 + lrow) * 128 +
                                          ks * 32 + lkb)));
#pragma unroll
            for (int mi = 0; mi < 2; mi++) {
                mma16816(d[mi][nj2 * 2], a[mi], b[0], b[2]);
                mma16816(d[mi][nj2 * 2 + 1], a[mi], b[1], b[3]);
            }
        }
    }

#pragma unroll
    for (int mi = 0; mi < 2; mi++) {
#pragma unroll
        for (int half = 0; half < 2; half++) {
            int r = wm + mi * 16 + half * 8 + (ln >> 2);
            int oy = oy0 + (r >> 4), ox = ox0 + (r & 15);
            size_t base = (((size_t)n * 64 + oy) * 64 + ox) * 128;
#pragma unroll
            for (int nj = 0; nj < 8; nj++) {
                int col = wn + nj * 8 + (ln & 3) * 2;
                float v0 = d[mi][nj][half * 2 + 0] + s_bias[col];
                float v1 = d[mi][nj][half * 2 + 1] + s_bias[col + 1];
                v0 = v0 > 0.0f ? v0 : 0.0f;
                v1 = v1 > 0.0f ? v1 : 0.0f;
                *(__half2*)(outH + base + col) = __floats2half2_rn(v0, v1);
            }
        }
    }
}

// ============================================================================
// HMMA implicit-GEMM conv (stride 2): proven, unchanged.
// ============================================================================
template <int CIN, int HOUT, int WOUT, int COUT, int OUTMODE>
__global__ __launch_bounds__(256, 2) void k_conv_mma(
    const __half* __restrict__ in, const __half* __restrict__ wH,
    const float* __restrict__ bias, __half* __restrict__ outH,
    float* __restrict__ pool) {
    constexpr int HIN = 2 * HOUT, WIN = 2 * WOUT;
    constexpr int NCH = CIN / 64;
    constexpr int ST = 9 * NCH;
    constexpr int BUF = 32768;

    extern __shared__ char smem[];
    float* s_bias = (float*)smem;
    float* s_red = (float*)(smem + 512);
    const uint32_t sbase = smem_u32(smem);
    const uint32_t TB = sbase + 4096;

    const int tid = threadIdx.x;
    const int warp = tid >> 5, ln = tid & 31;
    const int mtile = blockIdx.x, cob = blockIdx.y, n = blockIdx.z;
    const int oy0 = (mtile / (WOUT / 16)) * 8;
    const int ox0 = (mtile % (WOUT / 16)) * 16;
    const int co0 = cob * 128;

    if (tid < 128) s_bias[tid] = bias[co0 + tid];

    const int wm = (warp & 3) * 32;
    const int wn = (warp >> 2) * 64;
    const int lrow = (ln & 7) + ((ln >> 3) & 1) * 8;
    const int lkb = ((ln >> 4) & 1) * 16;

    float d[2][8][4];
#pragma unroll
    for (int mi = 0; mi < 2; mi++)
#pragma unroll
        for (int nj = 0; nj < 8; nj++)
#pragma unroll
            for (int q = 0; q < 4; q++) d[mi][nj][q] = 0.0f;

    auto stage_load = [&](int s) {
        const int buf = s & 1;
        const int p = s / NCH, q = s - p * NCH;
        const int ky = p / 3, kx = p - ky * 3;
        const int c0 = q * 64;
        const uint32_t tb = TB + buf * BUF;
        for (int seg = tid; seg < 1024; seg += 256) {
            int row = seg >> 3, j = seg & 7;
            int ty = row >> 4, tx = row & 15;
            int Y = 2 * (oy0 + ty) + ky - 1;
            int X = 2 * (ox0 + tx) + kx - 1;
            bool inb = (Y >= 0 && Y < HIN && X >= 0 && X < WIN);
            const void* src = in +
                ((((size_t)n * HIN + (inb ? Y : 0)) * WIN + (inb ? X : 0)) * CIN +
                 c0 + j * 8);
            cp_async16(tb + SWZ((uint32_t)(row * 128 + j * 16)), src, inb);
        }
        for (int seg = tid; seg < 1024; seg += 256) {
            int row = seg >> 3, j = seg & 7;
            const void* src =
                wH + (((size_t)(co0 + row) * 9 + p) * CIN + c0 + j * 8);
            cp_async16(tb + 16384 + SWZ((uint32_t)(row * 128 + j * 16)), src, true);
        }
        cp_commit();
    };

    stage_load(0);
    for (int s = 0; s < ST; s++) {
        if (s + 1 < ST) {
            stage_load(s + 1);
            asm volatile("cp.async.wait_group 1;" ::: "memory");
        } else {
            asm volatile("cp.async.wait_group 0;" ::: "memory");
        }
        __syncthreads();

        const uint32_t tb = TB + (s & 1) * BUF;
        const uint32_t bb = tb + 16384;
#pragma unroll
        for (int ks = 0; ks < 4; ks++) {
            uint32_t a[2][4];
#pragma unroll
            for (int mi = 0; mi < 2; mi++)
                ldsm4(a[mi], tb + SWZ((uint32_t)((wm + mi * 16 + lrow) * 128 +
                                                 ks * 32 + lkb)));
#pragma unroll
            for (int nj2 = 0; nj2 < 4; nj2++) {
                uint32_t b[4];
                ldsm4(b, bb + SWZ((uint32_t)((wn + nj2 * 16 + lrow) * 128 +
                                             ks * 32 + lkb)));
#pragma unroll
                for (int mi = 0; mi < 2; mi++) {
                    mma16816(d[mi][nj2 * 2], a[mi], b[0], b[2]);
                    mma16816(d[mi][nj2 * 2 + 1], a[mi], b[1], b[3]);
                }
            }
        }
        __syncthreads();
    }

    if (OUTMODE == 0) {
#pragma unroll
        for (int mi = 0; mi < 2; mi++) {
#pragma unroll
            for (int half = 0; half < 2; half++) {
                int r = wm + mi * 16 + half * 8 + (ln >> 2);
                int oy = oy0 + (r >> 4), ox = ox0 + (r & 15);
                size_t base = (((size_t)n * HOUT + oy) * WOUT + ox) * COUT + co0;
#pragma unroll
                for (int nj = 0; nj < 8; nj++) {
                    int col = wn + nj * 8 + (ln & 3) * 2;
                    float v0 = d[mi][nj][half * 2 + 0] + s_bias[col];
                    float v1 = d[mi][nj][half * 2 + 1] + s_bias[col + 1];
                    v0 = v0 > 0.0f ? v0 : 0.0f;
                    v1 = v1 > 0.0f ? v1 : 0.0f;
                    *(__half2*)(outH + base + col) = __floats2half2_rn(v0, v1);
                }
            }
        }
    } else {
        float sv[16];
#pragma unroll
        for (int nj = 0; nj < 8; nj++) {
            int col0 = wn + nj * 8 + (ln & 3) * 2;
            float b0 = s_bias[col0], b1 = s_bias[col0 + 1];
            float s0 = 0.0f, s1 = 0.0f;
#pragma unroll
            for (int mi = 0; mi < 2; mi++)
#pragma unroll
                for (int half = 0; half < 2; half++) {
                    float v0 = d[mi][nj][half * 2 + 0] + b0;
                    float v1 = d[mi][nj][half * 2 + 1] + b1;
                    s0 += v0 > 0.0f ? v0 : 0.0f;
                    s1 += v1 > 0.0f ? v1 : 0.0f;
                }
            sv[nj * 2] = s0;
            sv[nj * 2 + 1] = s1;
        }
#pragma unroll
        for (int off = 4; off < 32; off <<= 1)
#pragma unroll
            for (int k = 0; k < 16; k++)
                sv[k] += __shfl_xor_sync(0xffffffffu, sv[k], off);
        if (ln < 4) {
#pragma unroll
            for (int nj = 0; nj < 8; nj++) {
                s_red[warp * 64 + nj * 8 + ln * 2 + 0] = sv[nj * 2];
                s_red[warp * 64 + nj * 8 + ln * 2 + 1] = sv[nj * 2 + 1];
            }
        }
        __syncthreads();
        if (tid < 128) {
            int col = tid;
            int g = col >> 6, r = col & 63;
            float t = s_red[(g * 4 + 0) * 64 + r] + s_red[(g * 4 + 1) * 64 + r] +
                      s_red[(g * 4 + 2) * 64 + r] + s_red[(g * 4 + 3) * 64 + r];
            atomicAdd(&pool[n * 512 + co0 + col], t * (1.0f / 256.0f));
        }
    }
}

// ============================================================================
// FC1 (coalesced): warp per output. grid (128, 64), block 256.
// ============================================================================
__global__ void k_fc1(const float* __restrict__ pool, const float* __restrict__ w,
                      const float* __restrict__ b, float* __restrict__ out) {
    int n = blockIdx.y;
    __shared__ float sp[512];
    int tid = threadIdx.x;
    for (int k = tid; k < 512; k += 256) sp[k] = pool[n * 512 + k];
    __syncthreads();
    int warp = tid >> 5, ln = tid & 31;
    int o = blockIdx.x * 8 + warp;
    const float* wp = w + (size_t)o * 512;
    float acc = 0.0f;
#pragma unroll
    for (int k = ln; k < 512; k += 32) acc = fmaf(sp[k], wp[k], acc);
#pragma unroll
    for (int off = 16; off > 0; off >>= 1)
        acc += __shfl_down_sync(0xffffffffu, acc, off);
    if (ln == 0) {
        float v = acc + b[o];
        out[n * 1024 + o] = v > 0.0f ? v : 0.0f;
    }
}

// ============================================================================
// FC2: grid 64, block 320 (warp per output).
// ============================================================================
__global__ void k_fc2(const float* __restrict__ a, const float* __restrict__ w,
                      const float* __restrict__ b, float* __restrict__ out) {
    int n = blockIdx.x;
    int o = threadIdx.x >> 5, lane = threadIdx.x & 31;
    float acc = 0.0f;
    const float* ap = a + (size_t)n * 1024;
    const float* wp = w + (size_t)o * 1024;
    for (int k = lane; k < 1024; k += 32) acc = fmaf(ap[k], wp[k], acc);
#pragma unroll
    for (int off = 16; off > 0; off >>= 1)
        acc += __shfl_down_sync(0xffffffffu, acc, off);
    if (lane == 0) out[n * 10 + o] = acc + b[o];
}

// ============================================================================
// Host side
// ============================================================================
extern "C" void kernel_launch(void* const* d_in, const int* in_sizes, int n_in,
                              void* d_out, int out_size) {
    (void)in_sizes; (void)n_in; (void)out_size;
    const float* x   = (const float*)d_in[0];
    const float* w1  = (const float*)d_in[1];
    const float* s1  = (const float*)d_in[2];
    const float* b1  = (const float*)d_in[3];
    const float* w2  = (const float*)d_in[4];
    const float* s2  = (const float*)d_in[5];
    const float* b2  = (const float*)d_in[6];
    const float* w3  = (const float*)d_in[7];
    const float* s3  = (const float*)d_in[8];
    const float* b3  = (const float*)d_in[9];
    const float* fw1 = (const float*)d_in[10];
    const float* fs1 = (const float*)d_in[11];
    const float* fb1 = (const float*)d_in[12];
    const float* fw2 = (const float*)d_in[13];
    const float* fs2 = (const float*)d_in[14];
    const float* fb2 = (const float*)d_in[15];
    float* out = (float*)d_out;

    float *wm1, *fwm1, *fwm2, *pool, *a1;
    __half *w2h, *w3h, *h1, *h2;
    cudaGetSymbolAddress((void**)&wm1, g_wm1);
    cudaGetSymbolAddress((void**)&fwm1, g_fwm1);
    cudaGetSymbolAddress((void**)&fwm2, g_fwm2);
    cudaGetSymbolAddress((void**)&w2h, g_w2h);
    cudaGetSymbolAddress((void**)&w3h, g_w3h);
    cudaGetSymbolAddress((void**)&h1, g_h1);
    cudaGetSymbolAddress((void**)&h2, g_h2);
    cudaGetSymbolAddress((void**)&pool, g_pool);
    cudaGetSymbolAddress((void**)&a1, g_a1);

    auto c2 = k_conv_mma<128, 32, 32, 256, 0>;
    auto c3 = k_conv_mma<256, 16, 16, 512, 1>;
    const int mma_smem = 4096 + 2 * 32768;  // 69632
    cudaFuncSetAttribute((const void*)c2, cudaFuncAttributeMaxDynamicSharedMemorySize, mma_smem);
    cudaFuncSetAttribute((const void*)c3, cudaFuncAttributeMaxDynamicSharedMemorySize, mma_smem);
    const int c1_smem = 1024 + 2 * 16384;   // 33792

    MaskArgs ma;
    ma.s[0] = s1;  ma.w[0] = w1;  ma.wm[0] = wm1;     ma.n[0] = 3456;    ma.j[0] = 1728u;
    ma.s[1] = s2;  ma.w[1] = w2;  ma.wm[1] = nullptr; ma.n[1] = 294912;  ma.j[1] = 147456u;
    ma.s[2] = s3;  ma.w[2] = w3;  ma.wm[2] = nullptr; ma.n[2] = 1179648; ma.j[2] = 589824u;
    ma.s[3] = fs1; ma.w[3] = fw1; ma.wm[3] = fwm1;    ma.n[3] = 524288;  ma.j[3] = 262144u;
    ma.s[4] = fs2; ma.w[4] = fw2; ma.wm[4] = fwm2;    ma.n[4] = 10240;   ma.j[4] = 5120u;

    ConvApply ca;
    ca.s[0] = s2; ca.w[0] = w2; ca.dst[0] = w2h; ca.n[0] = 294912;  ca.cin[0] = 128;
    ca.s[1] = s3; ca.w[1] = w3; ca.dst[1] = w3h; ca.n[1] = 1179648; ca.cin[1] = 256;

    cudaStream_t sA = g_res.sA;

    // ---- fork ----
    cudaEventRecord(g_res.evStart, 0);

    // side A: pool memset + conv1 mask + conv1 (all hidden under mask chain)
    cudaStreamWaitEvent(sA, g_res.evStart, 0);
    cudaMemsetAsync(pool, 0, 64 * 512 * sizeof(float), sA);
    k_mask0<<<1, 256, 0, sA>>>(s1, w1, wm1);
    k_conv1_mma<<<dim3(32, 1, 64), 256, c1_smem, sA>>>(x, wm1, b1, h1);
    cudaEventRecord(g_res.evC1, sA);

    // main: ALL 4 big masks batched, 3 passes + tiny fixup
    k_histscan1<<<dim3(40, 4), 1024>>>(ma);
    k_histscan2<<<dim3(40, 4), 1024>>>(ma);
    k_tieapply<<<dim3(160, 4), 256>>>(ma, ca);
    k_fixup<<<4, 32>>>(ma, ca);

    // convs
    cudaStreamWaitEvent(0, g_res.evC1, 0);
    c2<<<dim3(8, 2, 64), 256, mma_smem>>>(h1, w2h, b2, h2, nullptr);
    c3<<<dim3(2, 4, 64), 256, mma_smem>>>(h2, w3h, b3, nullptr, pool);

    // head (FC masks already done in the batched chain)
    k_fc1<<<dim3(128, 64), 256>>>(pool, fwm1, fb1, a1);
    k_fc2<<<64, 320>>>(a1, fwm2, fb2, out);
}

// round 15
// speedup vs baseline: 1.0731x; 1.0242x over previous
#include <cuda_runtime.h>
#include <cuda_fp16.h>
#include <cstdint>

// ============================================================================
// Device scratch
// ============================================================================
__device__ float g_wm1[3456];
__device__ float g_fwm1[524288];
__device__ float g_fwm2[10240];

__device__ __align__(16) __half g_w2h[294912];
__device__ __align__(16) __half g_w3h[1179648];

__device__ __align__(16) __half g_h1[64u*64u*64u*128u];
__device__ __align__(16) __half g_h2[64u*32u*32u*256u];
__device__ float g_pool[64 * 512];
__device__ float g_a1[64 * 1024];

__device__ unsigned g_hist5[5][65536];
__device__ unsigned g_done[5];
struct Sel {
    unsigned b1, rank1, tbits, r, tieCount, idxThresh;
    unsigned tieIdx[2048];
};
__device__ Sel g_sel5[5];

struct MaskArgs {
    const float* s[5];
    const float* w[5];
    float* wm[5];
    int n[5];
    unsigned j[5];
};
struct ConvApply {
    const float* s[2];
    const float* w[2];
    __half* dst[2];
    int n[2];
    int cin[2];
};

__device__ __forceinline__ unsigned hperm(unsigned v) {
    return (v & 63u) * 1024u + (v >> 6);
}

// ============================================================================
// Persistent streams/events
// ============================================================================
struct GpuRes {
    cudaStream_t sA, sB;
    cudaEvent_t evStart, evC1, evT2, evW3, evFC;
    GpuRes() {
        cudaStreamCreateWithFlags(&sA, cudaStreamNonBlocking);
        cudaStreamCreateWithFlags(&sB, cudaStreamNonBlocking);
        cudaEventCreateWithFlags(&evStart, cudaEventDisableTiming);
        cudaEventCreateWithFlags(&evC1, cudaEventDisableTiming);
        cudaEventCreateWithFlags(&evT2, cudaEventDisableTiming);
        cudaEventCreateWithFlags(&evW3, cudaEventDisableTiming);
        cudaEventCreateWithFlags(&evFC, cudaEventDisableTiming);
    }
};
static GpuRes g_res;

// ============================================================================
// PTX helpers
// ============================================================================
#define SWZ(o) ((o) ^ (((o) >> 3) & 0x70))

__device__ __forceinline__ uint32_t smem_u32(const void* p) {
    uint32_t a;
    asm("{ .reg .u64 t; cvta.to.shared.u64 t, %1; cvt.u32.u64 %0, t; }"
        : "=r"(a) : "l"(p));
    return a;
}
__device__ __forceinline__ void cp_async16(uint32_t dst, const void* src, bool inb) {
    int sz = inb ? 16 : 0;
    asm volatile("cp.async.cg.shared.global [%0], [%1], 16, %2;\n"
                 :: "r"(dst), "l"(src), "r"(sz));
}
__device__ __forceinline__ void cp_commit() {
    asm volatile("cp.async.commit_group;\n" ::: "memory");
}
__device__ __forceinline__ void ldsm4(uint32_t* r, uint32_t addr) {
    asm volatile("ldmatrix.sync.aligned.m8n8.x4.shared.b16 {%0,%1,%2,%3}, [%4];"
                 : "=r"(r[0]), "=r"(r[1]), "=r"(r[2]), "=r"(r[3]) : "r"(addr));
}
__device__ __forceinline__ void mma16816(float* d, const uint32_t* a,
                                         uint32_t b0, uint32_t b1) {
    asm volatile(
        "mma.sync.aligned.m16n8k16.row.col.f32.f16.f16.f32 "
        "{%0,%1,%2,%3}, {%4,%5,%6,%7}, {%8,%9}, {%0,%1,%2,%3};"
        : "+f"(d[0]), "+f"(d[1]), "+f"(d[2]), "+f"(d[3])
        : "r"(a[0]), "r"(a[1]), "r"(a[2]), "r"(a[3]), "r"(b0), "r"(b1));
}

// ============================================================================
// k_mask0: exact select+apply for conv1 scores (n=3456, j=1728), 1 block.
// ============================================================================
__global__ __launch_bounds__(256) void k_mask0(const float* __restrict__ s,
                                               const float* __restrict__ w,
                                               float* __restrict__ wm) {
    constexpr int N = 3456;
    constexpr unsigned J = 1728;
    __shared__ unsigned sv[N];
    __shared__ unsigned wred[8];
    __shared__ unsigned t_sh, r_sh, tieCnt, idx_sh;
    __shared__ unsigned tieIdx[128];
    const int tid = threadIdx.x;
    const int lane = tid & 31, wid = tid >> 5;

    for (int i = tid; i < N; i += 256) sv[i] = __float_as_uint(fabsf(s[i]));
    if (tid == 0) { t_sh = 0; r_sh = J; }
    __syncthreads();

    for (int bit = 31; bit >= 0; bit--) {
        const unsigned m = 1u << bit;
        const unsigned hiMask = ~((m << 1) - 1u);
        const unsigned t = t_sh;
        unsigned local = 0;
        for (int i = tid; i < N; i += 256)
            if (((sv[i] ^ t) & hiMask) == 0 && !(sv[i] & m)) local++;
#pragma unroll
        for (int o = 16; o > 0; o >>= 1)
            local += __shfl_down_sync(0xffffffffu, local, o);
        if (lane == 0) wred[wid] = local;
        __syncthreads();
        if (tid == 0) {
            unsigned c = 0;
            for (int k = 0; k < 8; k++) c += wred[k];
            if (r_sh >= c) { t_sh |= m; r_sh -= c; }
        }
        __syncthreads();
    }

    if (tid == 0) tieCnt = 0;
    __syncthreads();
    const unsigned t = t_sh;
    for (int i = tid; i < N; i += 256)
        if (sv[i] == t) {
            unsigned p = atomicAdd(&tieCnt, 1u);
            if (p < 128) tieIdx[p] = (unsigned)i;
        }
    __syncthreads();
    if (tid == 0) {
        unsigned nt = tieCnt;
        if (nt > 128) nt = 128;
        for (unsigned i = 1; i < nt; i++) {
            unsigned v = tieIdx[i];
            int j = (int)i;
            while (j > 0 && tieIdx[j - 1] > v) { tieIdx[j] = tieIdx[j - 1]; j--; }
            tieIdx[j] = v;
        }
        unsigned r = r_sh;
        if (nt == 0) idx_sh = 0;
        else { if (r >= nt) r = nt - 1; idx_sh = tieIdx[r]; }
    }
    __syncthreads();
    const unsigned it = idx_sh;
    for (int i = tid; i < N; i += 256) {
        bool keep = (sv[i] > t) || (sv[i] == t && (unsigned)i >= it);
        wm[i] = keep ? w[i] : 0.0f;
    }
}

// ============================================================================
// Fused histogram+scan passes (last block scans). grid (G, cnt), block 1024.
// ============================================================================
__global__ __launch_bounds__(1024) void k_histscan1(MaskArgs a, int base) {
    int arr = base + blockIdx.y;
    const float* s = a.s[arr];
    int n = a.n[arr];
    unsigned* hist = g_hist5[arr];
    __shared__ unsigned wsum[32];
    __shared__ unsigned lastFlag;
    int tid = threadIdx.x;
    for (int i = blockIdx.x * 1024 + tid; i < n; i += gridDim.x * 1024) {
        unsigned b = __float_as_uint(fabsf(s[i]));
        atomicAdd(&hist[hperm(b >> 16)], 1u);
    }
    __threadfence();
    __syncthreads();
    if (tid == 0) {
        unsigned old = atomicAdd(&g_done[arr], 1u);
        lastFlag = (old == gridDim.x - 1) ? 1u : 0u;
        if (lastFlag) g_done[arr] = 0;
    }
    __syncthreads();
    if (!lastFlag) return;
    __threadfence();

    unsigned target = a.j[arr];
    int lane = tid & 31, wid = tid >> 5;
    unsigned local = 0;
#pragma unroll
    for (int k = 0; k < 64; k++) local += hist[k * 1024 + tid];
    unsigned inc = local;
#pragma unroll
    for (int o = 1; o < 32; o <<= 1) {
        unsigned y = __shfl_up_sync(0xffffffffu, inc, o);
        if (lane >= o) inc += y;
    }
    if (lane == 31) wsum[wid] = inc;
    __syncthreads();
    if (wid == 0) {
        unsigned v = wsum[lane];
        unsigned iv = v;
#pragma unroll
        for (int o = 1; o < 32; o <<= 1) {
            unsigned y = __shfl_up_sync(0xffffffffu, iv, o);
            if (lane >= o) iv += y;
        }
        wsum[lane] = iv - v;
    }
    __syncthreads();
    unsigned run = wsum[wid] + (inc - local);
#pragma unroll
    for (int k = 0; k < 64; k++) {
        unsigned h = hist[k * 1024 + tid];
        if (h && run <= target && target < run + h) {
            g_sel5[arr].b1 = (unsigned)(tid * 64 + k);
            g_sel5[arr].rank1 = target - run;
        }
        run += h;
        hist[k * 1024 + tid] = 0;
    }
}

__global__ __launch_bounds__(1024) void k_histscan2(MaskArgs a, int base) {
    int arr = base + blockIdx.y;
    const float* s = a.s[arr];
    int n = a.n[arr];
    unsigned* hist = g_hist5[arr];
    __shared__ unsigned wsum[32];
    __shared__ unsigned lastFlag;
    int tid = threadIdx.x;
    unsigned b1 = g_sel5[arr].b1;
    for (int i = blockIdx.x * 1024 + tid; i < n; i += gridDim.x * 1024) {
        unsigned b = __float_as_uint(fabsf(s[i]));
        if ((b >> 16) == b1) atomicAdd(&hist[hperm(b & 0xFFFFu)], 1u);
    }
    __threadfence();
    __syncthreads();
    if (tid == 0) {
        unsigned old = atomicAdd(&g_done[arr], 1u);
        lastFlag = (old == gridDim.x - 1) ? 1u : 0u;
        if (lastFlag) g_done[arr] = 0;
    }
    __syncthreads();
    if (!lastFlag) return;
    __threadfence();

    int lane = tid & 31, wid = tid >> 5;
    unsigned target = g_sel5[arr].rank1;
    unsigned local = 0;
#pragma unroll
    for (int k = 0; k < 64; k++) local += hist[k * 1024 + tid];
    unsigned inc = local;
#pragma unroll
    for (int o = 1; o < 32; o <<= 1) {
        unsigned y = __shfl_up_sync(0xffffffffu, inc, o);
        if (lane >= o) inc += y;
    }
    if (lane == 31) wsum[wid] = inc;
    __syncthreads();
    if (wid == 0) {
        unsigned v = wsum[lane];
        unsigned iv = v;
#pragma unroll
        for (int o = 1; o < 32; o <<= 1) {
            unsigned y = __shfl_up_sync(0xffffffffu, iv, o);
            if (lane >= o) iv += y;
        }
        wsum[lane] = iv - v;
    }
    __syncthreads();
    if (tid == 0) g_sel5[arr].tieCount = 0;
    unsigned run = wsum[wid] + (inc - local);
#pragma unroll
    for (int k = 0; k < 64; k++) {
        unsigned h = hist[k * 1024 + tid];
        if (h && run <= target && target < run + h) {
            g_sel5[arr].tbits = (g_sel5[arr].b1 << 16) | (unsigned)(tid * 64 + k);
            g_sel5[arr].r = target - run;
        }
        run += h;
        hist[k * 1024 + tid] = 0;
    }
}

// ============================================================================
// tieapply with folded fixup: one pass writes outputs (b==t tentatively
// dropped, index recorded); last block sorts ties and rewrites the keepers.
// Conv arrays (arr 1,2) -> fp16 [co][pos][ci]; FC arrays (3,4) -> fp32 flat.
// grid (G, cnt), block 256.
// ============================================================================
__global__ void k_tieapply(MaskArgs a, ConvApply ca, int base) {
    int arr = base + blockIdx.y;
    const float* s = a.s[arr];
    const float* w = a.w[arr];
    int n = a.n[arr];
    unsigned t = g_sel5[arr].tbits;
    const bool isConv = (arr <= 2);
    if (isConv) {
        __half* dst = ca.dst[arr - 1];
        int cin = ca.cin[arr - 1];
        for (int i = blockIdx.x * blockDim.x + threadIdx.x; i < n;
             i += gridDim.x * blockDim.x) {
            unsigned b = __float_as_uint(fabsf(s[i]));
            if (b == t) {
                unsigned p = atomicAdd(&g_sel5[arr].tieCount, 1u);
                if (p < 2048) g_sel5[arr].tieIdx[p] = (unsigned)i;
            }
            float v = (b > t) ? w[i] : 0.0f;
            int p9 = i % 9;
            int ci = (i / 9) % cin;
            int co = i / (9 * cin);
            dst[((size_t)co * 9 + p9) * cin + ci] = __float2half_rn(v);
        }
    } else {
        float* wm = a.wm[arr];
        for (int i = blockIdx.x * blockDim.x + threadIdx.x; i < n;
             i += gridDim.x * blockDim.x) {
            unsigned b = __float_as_uint(fabsf(s[i]));
            if (b == t) {
                unsigned p = atomicAdd(&g_sel5[arr].tieCount, 1u);
                if (p < 2048) g_sel5[arr].tieIdx[p] = (unsigned)i;
            }
            wm[i] = (b > t) ? w[i] : 0.0f;
        }
    }
    __threadfence();
    __syncthreads();
    if (threadIdx.x == 0) {
        unsigned old = atomicAdd(&g_done[arr], 1u);
        if (old == gridDim.x - 1) {
            g_done[arr] = 0;
            __threadfence();
            Sel& sel = g_sel5[arr];
            unsigned nt = sel.tieCount;
            if (nt > 2048) nt = 2048;
            if (nt == 0) return;
            for (unsigned i = 1; i < nt; i++) {
                unsigned v = sel.tieIdx[i];
                int j = (int)i;
                while (j > 0 && sel.tieIdx[j - 1] > v) {
                    sel.tieIdx[j] = sel.tieIdx[j - 1];
                    j--;
                }
                sel.tieIdx[j] = v;
            }
            unsigned r = sel.r;
            if (r >= nt) r = nt - 1;
            for (unsigned k = r; k < nt; k++) {
                unsigned i = sel.tieIdx[k];
                float v = w[i];
                if (isConv) {
                    int cin = ca.cin[arr - 1];
                    int p9 = i % 9;
                    int ci = (i / 9) % cin;
                    int co = i / (9 * cin);
                    ca.dst[arr - 1][((size_t)co * 9 + p9) * cin + ci] =
                        __float2half_rn(v);
                } else {
                    a.wm[arr][i] = v;
                }
            }
        }
    }
}

// ============================================================================
// conv1 via HMMA implicit GEMM: K=27 (pad 32), M=128 px, N=128 co.
// ============================================================================
__global__ __launch_bounds__(256) void k_conv1_mma(
    const float* __restrict__ x, const float* __restrict__ wm1,
    const float* __restrict__ bias, __half* __restrict__ outH) {
    extern __shared__ char smem[];
    float* s_bias = (float*)smem;
    const uint32_t sbase = smem_u32(smem);
    const uint32_t TA = sbase + 1024;
    const uint32_t TBB = TA + 16384;
    __half* sAh = (__half*)(smem + 1024);
    __half* sBh = (__half*)(smem + 1024 + 16384);

    const int tid = threadIdx.x;
    const int warp = tid >> 5, ln = tid & 31;
    const int mtile = blockIdx.x, n = blockIdx.z;
    const int oy0 = (mtile >> 2) * 8;
    const int ox0 = (mtile & 3) * 16;

    if (tid < 128) s_bias[tid] = bias[tid];

    for (int idx = tid; idx < 128 * 32; idx += 256) {
        int row = idx >> 5, k = idx & 31;
        float v = 0.0f;
        if (k < 27) {
            int cc = k / 9, rem = k - cc * 9;
            int ky = rem / 3, kx = rem - ky * 3;
            int Y = oy0 + (row >> 4) + ky - 1;
            int X = ox0 + (row & 15) + kx - 1;
            if (Y >= 0 && Y < 64 && X >= 0 && X < 64)
                v = x[(((size_t)n * 3 + cc) * 64 + Y) * 64 + X];
        }
        *(__half*)((char*)sAh + SWZ((uint32_t)(row * 128 + k * 2))) =
            __float2half_rn(v);
    }
    for (int idx = tid; idx < 128 * 32; idx += 256) {
        int row = idx >> 5, k = idx & 31;
        float v = (k < 27) ? wm1[row * 27 + k] : 0.0f;
        *(__half*)((char*)sBh + SWZ((uint32_t)(row * 128 + k * 2))) =
            __float2half_rn(v);
    }
    __syncthreads();

    const int wm = (warp & 3) * 32;
    const int wn = (warp >> 2) * 64;
    const int lrow = (ln & 7) + ((ln >> 3) & 1) * 8;
    const int lkb = ((ln >> 4) & 1) * 16;

    float d[2][8][4];
#pragma unroll
    for (int mi = 0; mi < 2; mi++)
#pragma unroll
        for (int nj = 0; nj < 8; nj++)
#pragma unroll
            for (int q = 0; q < 4; q++) d[mi][nj][q] = 0.0f;

#pragma unroll
    for (int ks = 0; ks < 2; ks++) {
        uint32_t a[2][4];
#pragma unroll
        for (int mi = 0; mi < 2; mi++)
            ldsm4(a[mi], TA + SWZ((uint32_t)((wm + mi * 16 + lrow) * 128 +
                                             ks * 32 + lkb)));
#pragma unroll
        for (int nj2 = 0; nj2 < 4; nj2++) {
            uint32_t b[4];
            ldsm4(b, TBB + SWZ((uint32_t)((wn + nj2 * 16 + lrow) * 128 +
                                          ks * 32 + lkb)));
#pragma unroll
            for (int mi = 0; mi < 2; mi++) {
                mma16816(d[mi][nj2 * 2], a[mi], b[0], b[2]);
                mma16816(d[mi][nj2 * 2 + 1], a[mi], b[1], b[3]);
            }
        }
    }

#pragma unroll
    for (int mi = 0; mi < 2; mi++) {
#pragma unroll
        for (int half = 0; half < 2; half++) {
            int r = wm + mi * 16 + half * 8 + (ln >> 2);
            int oy = oy0 + (r >> 4), ox = ox0 + (r & 15);
            size_t base = (((size_t)n * 64 + oy) * 64 + ox) * 128;
#pragma unroll
            for (int nj = 0; nj < 8; nj++) {
                int col = wn + nj * 8 + (ln & 3) * 2;
                float v0 = d[mi][nj][half * 2 + 0] + s_bias[col];
                float v1 = d[mi][nj][half * 2 + 1] + s_bias[col + 1];
                v0 = v0 > 0.0f ? v0 : 0.0f;
                v1 = v1 > 0.0f ? v1 : 0.0f;
                *(__half2*)(outH + base + col) = __floats2half2_rn(v0, v1);
            }
        }
    }
}

// ============================================================================
// HMMA implicit-GEMM conv (stride 2): proven, unchanged.
// ============================================================================
template <int CIN, int HOUT, int WOUT, int COUT, int OUTMODE>
__global__ __launch_bounds__(256, 2) void k_conv_mma(
    const __half* __restrict__ in, const __half* __restrict__ wH,
    const float* __restrict__ bias, __half* __restrict__ outH,
    float* __restrict__ pool) {
    constexpr int HIN = 2 * HOUT, WIN = 2 * WOUT;
    constexpr int NCH = CIN / 64;
    constexpr int ST = 9 * NCH;
    constexpr int BUF = 32768;

    extern __shared__ char smem[];
    float* s_bias = (float*)smem;
    float* s_red = (float*)(smem + 512);
    const uint32_t sbase = smem_u32(smem);
    const uint32_t TB = sbase + 4096;

    const int tid = threadIdx.x;
    const int warp = tid >> 5, ln = tid & 31;
    const int mtile = blockIdx.x, cob = blockIdx.y, n = blockIdx.z;
    const int oy0 = (mtile / (WOUT / 16)) * 8;
    const int ox0 = (mtile % (WOUT / 16)) * 16;
    const int co0 = cob * 128;

    if (tid < 128) s_bias[tid] = bias[co0 + tid];

    const int wm = (warp & 3) * 32;
    const int wn = (warp >> 2) * 64;
    const int lrow = (ln & 7) + ((ln >> 3) & 1) * 8;
    const int lkb = ((ln >> 4) & 1) * 16;

    float d[2][8][4];
#pragma unroll
    for (int mi = 0; mi < 2; mi++)
#pragma unroll
        for (int nj = 0; nj < 8; nj++)
#pragma unroll
            for (int q = 0; q < 4; q++) d[mi][nj][q] = 0.0f;

    auto stage_load = [&](int s) {
        const int buf = s & 1;
        const int p = s / NCH, q = s - p * NCH;
        const int ky = p / 3, kx = p - ky * 3;
        const int c0 = q * 64;
        const uint32_t tb = TB + buf * BUF;
        for (int seg = tid; seg < 1024; seg += 256) {
            int row = seg >> 3, j = seg & 7;
            int ty = row >> 4, tx = row & 15;
            int Y = 2 * (oy0 + ty) + ky - 1;
            int X = 2 * (ox0 + tx) + kx - 1;
            bool inb = (Y >= 0 && Y < HIN && X >= 0 && X < WIN);
            const void* src = in +
                ((((size_t)n * HIN + (inb ? Y : 0)) * WIN + (inb ? X : 0)) * CIN +
                 c0 + j * 8);
            cp_async16(tb + SWZ((uint32_t)(row * 128 + j * 16)), src, inb);
        }
        for (int seg = tid; seg < 1024; seg += 256) {
            int row = seg >> 3, j = seg & 7;
            const void* src =
                wH + (((size_t)(co0 + row) * 9 + p) * CIN + c0 + j * 8);
            cp_async16(tb + 16384 + SWZ((uint32_t)(row * 128 + j * 16)), src, true);
        }
        cp_commit();
    };

    stage_load(0);
    for (int s = 0; s < ST; s++) {
        if (s + 1 < ST) {
            stage_load(s + 1);
            asm volatile("cp.async.wait_group 1;" ::: "memory");
        } else {
            asm volatile("cp.async.wait_group 0;" ::: "memory");
        }
        __syncthreads();

        const uint32_t tb = TB + (s & 1) * BUF;
        const uint32_t bb = tb + 16384;
#pragma unroll
        for (int ks = 0; ks < 4; ks++) {
            uint32_t a[2][4];
#pragma unroll
            for (int mi = 0; mi < 2; mi++)
                ldsm4(a[mi], tb + SWZ((uint32_t)((wm + mi * 16 + lrow) * 128 +
                                                 ks * 32 + lkb)));
#pragma unroll
            for (int nj2 = 0; nj2 < 4; nj2++) {
                uint32_t b[4];
                ldsm4(b, bb + SWZ((uint32_t)((wn + nj2 * 16 + lrow) * 128 +
                                             ks * 32 + lkb)));
#pragma unroll
                for (int mi = 0; mi < 2; mi++) {
                    mma16816(d[mi][nj2 * 2], a[mi], b[0], b[2]);
                    mma16816(d[mi][nj2 * 2 + 1], a[mi], b[1], b[3]);
                }
            }
        }
        __syncthreads();
    }

    if (OUTMODE == 0) {
#pragma unroll
        for (int mi = 0; mi < 2; mi++) {
#pragma unroll
            for (int half = 0; half < 2; half++) {
                int r = wm + mi * 16 + half * 8 + (ln >> 2);
                int oy = oy0 + (r >> 4), ox = ox0 + (r & 15);
                size_t base = (((size_t)n * HOUT + oy) * WOUT + ox) * COUT + co0;
#pragma unroll
                for (int nj = 0; nj < 8; nj++) {
                    int col = wn + nj * 8 + (ln & 3) * 2;
                    float v0 = d[mi][nj][half * 2 + 0] + s_bias[col];
                    float v1 = d[mi][nj][half * 2 + 1] + s_bias[col + 1];
                    v0 = v0 > 0.0f ? v0 : 0.0f;
                    v1 = v1 > 0.0f ? v1 : 0.0f;
                    *(__half2*)(outH + base + col) = __floats2half2_rn(v0, v1);
                }
            }
        }
    } else {
        float sv[16];
#pragma unroll
        for (int nj = 0; nj < 8; nj++) {
            int col0 = wn + nj * 8 + (ln & 3) * 2;
            float b0 = s_bias[col0], b1 = s_bias[col0 + 1];
            float s0 = 0.0f, s1 = 0.0f;
#pragma unroll
            for (int mi = 0; mi < 2; mi++)
#pragma unroll
                for (int half = 0; half < 2; half++) {
                    float v0 = d[mi][nj][half * 2 + 0] + b0;
                    float v1 = d[mi][nj][half * 2 + 1] + b1;
                    s0 += v0 > 0.0f ? v0 : 0.0f;
                    s1 += v1 > 0.0f ? v1 : 0.0f;
                }
            sv[nj * 2] = s0;
            sv[nj * 2 + 1] = s1;
        }
#pragma unroll
        for (int off = 4; off < 32; off <<= 1)
#pragma unroll
            for (int k = 0; k < 16; k++)
                sv[k] += __shfl_xor_sync(0xffffffffu, sv[k], off);
        if (ln < 4) {
#pragma unroll
            for (int nj = 0; nj < 8; nj++) {
                s_red[warp * 64 + nj * 8 + ln * 2 + 0] = sv[nj * 2];
                s_red[warp * 64 + nj * 8 + ln * 2 + 1] = sv[nj * 2 + 1];
            }
        }
        __syncthreads();
        if (tid < 128) {
            int col = tid;
            int g = col >> 6, r = col & 63;
            float t = s_red[(g * 4 + 0) * 64 + r] + s_red[(g * 4 + 1) * 64 + r] +
                      s_red[(g * 4 + 2) * 64 + r] + s_red[(g * 4 + 3) * 64 + r];
            atomicAdd(&pool[n * 512 + co0 + col], t * (1.0f / 256.0f));
        }
    }
}

// ============================================================================
// FC1 (coalesced): warp per output. grid (128, 64), block 256.
// ============================================================================
__global__ void k_fc1(const float* __restrict__ pool, const float* __restrict__ w,
                      const float* __restrict__ b, float* __restrict__ out) {
    int n = blockIdx.y;
    __shared__ float sp[512];
    int tid = threadIdx.x;
    for (int k = tid; k < 512; k += 256) sp[k] = pool[n * 512 + k];
    __syncthreads();
    int warp = tid >> 5, ln = tid & 31;
    int o = blockIdx.x * 8 + warp;
    const float* wp = w + (size_t)o * 512;
    float acc = 0.0f;
#pragma unroll
    for (int k = ln; k < 512; k += 32) acc = fmaf(sp[k], wp[k], acc);
#pragma unroll
    for (int off = 16; off > 0; off >>= 1)
        acc += __shfl_down_sync(0xffffffffu, acc, off);
    if (ln == 0) {
        float v = acc + b[o];
        out[n * 1024 + o] = v > 0.0f ? v : 0.0f;
    }
}

// ============================================================================
// FC2: grid 64, block 320 (warp per output).
// ============================================================================
__global__ void k_fc2(const float* __restrict__ a, const float* __restrict__ w,
                      const float* __restrict__ b, float* __restrict__ out) {
    int n = blockIdx.x;
    int o = threadIdx.x >> 5, lane = threadIdx.x & 31;
    float acc = 0.0f;
    const float* ap = a + (size_t)n * 1024;
    const float* wp = w + (size_t)o * 1024;
    for (int k = lane; k < 1024; k += 32) acc = fmaf(ap[k], wp[k], acc);
#pragma unroll
    for (int off = 16; off > 0; off >>= 1)
        acc += __shfl_down_sync(0xffffffffu, acc, off);
    if (lane == 0) out[n * 10 + o] = acc + b[o];
}

// ============================================================================
// Host side
// ============================================================================
extern "C" void kernel_launch(void* const* d_in, const int* in_sizes, int n_in,
                              void* d_out, int out_size) {
    (void)in_sizes; (void)n_in; (void)out_size;
    const float* x   = (const float*)d_in[0];
    const float* w1  = (const float*)d_in[1];
    const float* s1  = (const float*)d_in[2];
    const float* b1  = (const float*)d_in[3];
    const float* w2  = (const float*)d_in[4];
    const float* s2  = (const float*)d_in[5];
    const float* b2  = (const float*)d_in[6];
    const float* w3  = (const float*)d_in[7];
    const float* s3  = (const float*)d_in[8];
    const float* b3  = (const float*)d_in[9];
    const float* fw1 = (const float*)d_in[10];
    const float* fs1 = (const float*)d_in[11];
    const float* fb1 = (const float*)d_in[12];
    const float* fw2 = (const float*)d_in[13];
    const float* fs2 = (const float*)d_in[14];
    const float* fb2 = (const float*)d_in[15];
    float* out = (float*)d_out;

    float *wm1, *fwm1, *fwm2, *pool, *a1;
    __half *w2h, *w3h, *h1, *h2;
    cudaGetSymbolAddress((void**)&wm1, g_wm1);
    cudaGetSymbolAddress((void**)&fwm1, g_fwm1);
    cudaGetSymbolAddress((void**)&fwm2, g_fwm2);
    cudaGetSymbolAddress((void**)&w2h, g_w2h);
    cudaGetSymbolAddress((void**)&w3h, g_w3h);
    cudaGetSymbolAddress((void**)&h1, g_h1);
    cudaGetSymbolAddress((void**)&h2, g_h2);
    cudaGetSymbolAddress((void**)&pool, g_pool);
    cudaGetSymbolAddress((void**)&a1, g_a1);

    auto c2 = k_conv_mma<128, 32, 32, 256, 0>;
    auto c3 = k_conv_mma<256, 16, 16, 512, 1>;
    const int mma_smem = 4096 + 2 * 32768;  // 69632
    cudaFuncSetAttribute((const void*)c2, cudaFuncAttributeMaxDynamicSharedMemorySize, mma_smem);
    cudaFuncSetAttribute((const void*)c3, cudaFuncAttributeMaxDynamicSharedMemorySize, mma_smem);
    const int c1_smem = 1024 + 2 * 16384;   // 33792

    MaskArgs ma;
    ma.s[0] = s1;  ma.w[0] = w1;  ma.wm[0] = wm1;     ma.n[0] = 3456;    ma.j[0] = 1728u;
    ma.s[1] = s2;  ma.w[1] = w2;  ma.wm[1] = nullptr; ma.n[1] = 294912;  ma.j[1] = 147456u;
    ma.s[2] = s3;  ma.w[2] = w3;  ma.wm[2] = nullptr; ma.n[2] = 1179648; ma.j[2] = 589824u;
    ma.s[3] = fs1; ma.w[3] = fw1; ma.wm[3] = fwm1;    ma.n[3] = 524288;  ma.j[3] = 262144u;
    ma.s[4] = fs2; ma.w[4] = fw2; ma.wm[4] = fwm2;    ma.n[4] = 10240;   ma.j[4] = 5120u;

    ConvApply ca;
    ca.s[0] = s2; ca.w[0] = w2; ca.dst[0] = w2h; ca.n[0] = 294912;  ca.cin[0] = 128;
    ca.s[1] = s3; ca.w[1] = w3; ca.dst[1] = w3h; ca.n[1] = 1179648; ca.cin[1] = 256;

    cudaStream_t sA = g_res.sA, sB = g_res.sB;

    // ---- fork ----
    cudaEventRecord(g_res.evStart, 0);

    // side A: pool memset + conv1 mask + conv1 (hidden under mask chain)
    cudaStreamWaitEvent(sA, g_res.evStart, 0);
    cudaMemsetAsync(pool, 0, 64 * 512 * sizeof(float), sA);
    k_mask0<<<1, 256, 0, sA>>>(s1, w1, wm1);
    k_conv1_mma<<<dim3(32, 1, 64), 256, c1_smem, sA>>>(x, wm1, b1, h1);
    cudaEventRecord(g_res.evC1, sA);

    // main: selection for conv weight arrays {w2, w3}
    k_histscan1<<<dim3(40, 2), 1024>>>(ma, 1);
    k_histscan2<<<dim3(40, 2), 1024>>>(ma, 1);
    cudaEventRecord(g_res.evT2, 0);  // tbits/r ready for arrays 1,2

    // main: apply w2 only (small, critical for conv2)
    k_tieapply<<<dim3(120, 1), 256>>>(ma, ca, 1);

    // side B: apply w3 (big write) concurrent with conv2; then FC mask chain
    cudaStreamWaitEvent(sB, g_res.evT2, 0);
    k_tieapply<<<dim3(160, 1), 256, 0, sB>>>(ma, ca, 2);
    cudaEventRecord(g_res.evW3, sB);
    k_histscan1<<<dim3(40, 2), 1024, 0, sB>>>(ma, 3);
    k_histscan2<<<dim3(40, 2), 1024, 0, sB>>>(ma, 3);
    k_tieapply<<<dim3(160, 2), 256, 0, sB>>>(ma, ca, 3);
    cudaEventRecord(g_res.evFC, sB);

    // main: convs
    cudaStreamWaitEvent(0, g_res.evC1, 0);
    c2<<<dim3(8, 2, 64), 256, mma_smem>>>(h1, w2h, b2, h2, nullptr);
    cudaStreamWaitEvent(0, g_res.evW3, 0);
    c3<<<dim3(2, 4, 64), 256, mma_smem>>>(h2, w3h, b3, nullptr, pool);

    // head
    cudaStreamWaitEvent(0, g_res.evFC, 0);
    k_fc1<<<dim3(128, 64), 256>>>(pool, fwm1, fb1, a1);
    k_fc2<<<64, 320>>>(a1, fwm2, fb2, out);
}